// round 2
// baseline (speedup 1.0000x reference)
#include <cuda_runtime.h>
#include <cstdint>
#include <cstddef>

#define N_USERS   100000
#define N_NODES   500000
#define DIM       64
#define N_EDGES   2000000
#define BATCH     4096

#define SCAN_BLK  1024
#define N_SCAN_BLKS ((N_NODES + SCAN_BLK - 1) / SCAN_BLK)   // 489

// -------- device scratch (static, allocation-free) --------
__device__ float    g_XA[(size_t)N_NODES * DIM];   // layer buffers (only flagged rows valid)
__device__ float    g_XB[(size_t)N_NODES * DIM];
__device__ float    g_dinv[N_NODES];
__device__ unsigned g_deg[N_NODES];
__device__ unsigned g_cur[N_NODES];
__device__ int      g_rowptr[N_NODES + 1];
__device__ int      g_bsum[512];
__device__ int      g_csr_src[N_EDGES];
__device__ float    g_csr_w[N_EDGES];
__device__ char     g_f1[N_NODES];                 // rows needed at layer 1/2/3
__device__ char     g_f2[N_NODES];
__device__ char     g_f3[N_NODES];
__device__ float    g_acc[(size_t)3 * BATCH * DIM]; // batch accumulators [user|pos|neg]

// -------- init: zero counters + flags --------
__global__ void k_init() {
    int i = blockIdx.x * blockDim.x + threadIdx.x;
    if (i < N_NODES) {
        g_deg[i] = 0u; g_cur[i] = 0u;
        g_f1[i] = 0; g_f2[i] = 0; g_f3[i] = 0;
    }
}

__global__ void k_deg(const int* __restrict__ dst) {
    int e = blockIdx.x * blockDim.x + threadIdx.x;
    if (e < N_EDGES) atomicAdd(&g_deg[dst[e]], 1u);
}

__global__ void k_dinv() {
    int i = blockIdx.x * blockDim.x + threadIdx.x;
    if (i < N_NODES) {
        unsigned d = g_deg[i];
        g_dinv[i] = d ? rsqrtf((float)d) : 0.0f;
    }
}

// -------- 3-pass exclusive prefix scan of deg -> rowptr --------
__global__ void k_scanA() {
    __shared__ int sm[SCAN_BLK];
    int i = blockIdx.x * SCAN_BLK + threadIdx.x;
    int v = (i < N_NODES) ? (int)g_deg[i] : 0;
    sm[threadIdx.x] = v;
    __syncthreads();
    for (int off = 1; off < SCAN_BLK; off <<= 1) {
        int t = (threadIdx.x >= off) ? sm[threadIdx.x - off] : 0;
        __syncthreads();
        sm[threadIdx.x] += t;
        __syncthreads();
    }
    if (i < N_NODES) g_rowptr[i] = sm[threadIdx.x] - v;     // exclusive within block
    if (threadIdx.x == SCAN_BLK - 1) g_bsum[blockIdx.x] = sm[SCAN_BLK - 1];
}

__global__ void k_scanB() {   // one block of 512, scans N_SCAN_BLKS block sums
    __shared__ int sm[512];
    int v = (threadIdx.x < N_SCAN_BLKS) ? g_bsum[threadIdx.x] : 0;
    sm[threadIdx.x] = v;
    __syncthreads();
    for (int off = 1; off < 512; off <<= 1) {
        int t = (threadIdx.x >= off) ? sm[threadIdx.x - off] : 0;
        __syncthreads();
        sm[threadIdx.x] += t;
        __syncthreads();
    }
    g_bsum[threadIdx.x] = sm[threadIdx.x] - v;               // exclusive
}

__global__ void k_scanC() {
    int i = blockIdx.x * blockDim.x + threadIdx.x;
    if (i < N_NODES) g_rowptr[i] += g_bsum[i >> 10];
    if (i == 0) g_rowptr[N_NODES] = N_EDGES;
}

// -------- CSR scatter: group edges by dst, precompute weight --------
__global__ void k_scatter(const int* __restrict__ src, const int* __restrict__ dst) {
    int e = blockIdx.x * blockDim.x + threadIdx.x;
    if (e >= N_EDGES) return;
    int s = src[e], d = dst[e];
    int pos = g_rowptr[d] + (int)atomicAdd(&g_cur[d], 1u);
    g_csr_src[pos] = s;
    g_csr_w[pos]   = g_dinv[s] * g_dinv[d];
}

// -------- needed-node flags --------
__global__ void k_mark_batch(const int* __restrict__ u,
                             const int* __restrict__ p,
                             const int* __restrict__ n) {
    int t = blockIdx.x * blockDim.x + threadIdx.x;
    if (t >= 3 * BATCH) return;
    int idx = (t < BATCH) ? u[t]
            : (t < 2 * BATCH) ? p[t - BATCH]
                              : n[t - 2 * BATCH];
    g_f1[idx] = 1; g_f2[idx] = 1; g_f3[idx] = 1;
}

// if dst needed at layer L, its sources are needed at layer L-1
__global__ void k_expand(const int* __restrict__ src, const int* __restrict__ dst,
                         const char* __restrict__ f_next, char* __restrict__ f_prev) {
    int e = blockIdx.x * blockDim.x + threadIdx.x;
    if (e < N_EDGES && f_next[dst[e]]) f_prev[src[e]] = 1;
}

// -------- propagation: one warp per flagged dst row, register accumulate --------
__global__ void k_prop_csr(const float* __restrict__ x, float* __restrict__ y,
                           const char* __restrict__ flag) {
    int node = (blockIdx.x * blockDim.x + threadIdx.x) >> 5;
    int lane = threadIdx.x & 31;
    if (node >= N_NODES) return;
    if (!flag[node]) return;

    int beg = g_rowptr[node];
    int end = g_rowptr[node + 1];
    const float2* xf2 = (const float2*)x;
    float ax = 0.f, ay = 0.f;
    for (int e = beg; e < end; e++) {
        int   s = __ldg(g_csr_src + e);
        float w = __ldg(g_csr_w + e);
        float2 v = __ldg(xf2 + (size_t)s * 32 + lane);
        ax += v.x * w;
        ay += v.y * w;
    }
    ((float2*)y)[(size_t)node * 32 + lane] = make_float2(ax, ay);
}

// -------- batch accumulators --------
__global__ void k_init_acc(const float* __restrict__ emb,
                           const int* __restrict__ u,
                           const int* __restrict__ p,
                           const int* __restrict__ n) {
    int t = blockIdx.x * blockDim.x + threadIdx.x;
    if (t >= 3 * BATCH * (DIM / 4)) return;
    int row = t >> 4, c = t & 15;
    int idx = (row < BATCH) ? u[row]
            : (row < 2 * BATCH) ? p[row - BATCH]
                                : n[row - 2 * BATCH];
    ((float4*)g_acc)[t] = __ldg((const float4*)emb + (size_t)idx * 16 + c);
}

__global__ void k_gather_add(const float* __restrict__ x,
                             const int* __restrict__ u,
                             const int* __restrict__ p,
                             const int* __restrict__ n) {
    int t = blockIdx.x * blockDim.x + threadIdx.x;
    if (t >= 3 * BATCH * (DIM / 4)) return;
    int row = t >> 4, c = t & 15;
    int idx = (row < BATCH) ? u[row]
            : (row < 2 * BATCH) ? p[row - BATCH]
                                : n[row - 2 * BATCH];
    float4 v = __ldg((const float4*)x + (size_t)idx * 16 + c);
    float4* a = (float4*)g_acc + t;
    float4 av = *a;
    av.x += v.x; av.y += v.y; av.z += v.z; av.w += v.w;
    *a = av;
}

__global__ void k_zero_out(float* out) {
    if (threadIdx.x == 0 && blockIdx.x == 0) out[0] = 0.0f;
}

// -------- final BPR + L2 loss: one warp per batch element --------
__global__ void k_loss(const float* __restrict__ emb,
                       const int* __restrict__ user,
                       const int* __restrict__ pos,
                       const int* __restrict__ neg,
                       float* __restrict__ out) {
    int w = (blockIdx.x * blockDim.x + threadIdx.x) >> 5;
    int lane = threadIdx.x & 31;
    if (w >= BATCH) return;

    const float* U  = g_acc + (size_t)w * DIM;
    const float* P  = g_acc + (size_t)(BATCH + w) * DIM;
    const float* Nn = g_acc + (size_t)(2 * BATCH + w) * DIM;

    int ui = user[w], pi = pos[w], ni = neg[w];

    float pd = 0.f, nd = 0.f, sq = 0.f;
#pragma unroll
    for (int k = 0; k < 2; k++) {
        int j = lane + 32 * k;
        float uu = U[j], pp = P[j], nn = Nn[j];
        pd += uu * pp;
        nd += uu * nn;
        float a = __ldg(emb + (size_t)ui * DIM + j);
        float b = __ldg(emb + (size_t)pi * DIM + j);
        float c = __ldg(emb + (size_t)ni * DIM + j);
        sq += a * a + b * b + c * c;
    }
#pragma unroll
    for (int o = 16; o; o >>= 1) {
        pd += __shfl_xor_sync(0xffffffffu, pd, o);
        nd += __shfl_xor_sync(0xffffffffu, nd, o);
        sq += __shfl_xor_sync(0xffffffffu, sq, o);
    }
    if (lane == 0) {
        // acc rows = sums over 4 stacked layers; mean /4 each side -> dot scales 1/16
        float z = (nd - pd) * 0.0625f;
        float sp = fmaxf(z, 0.f) + log1pf(expf(-fabsf(z)));   // softplus(neg - pos)
        atomicAdd(out, (sp + 5e-5f * sq) * (1.0f / BATCH));
    }
}

extern "C" void kernel_launch(void* const* d_in, const int* in_sizes, int n_in,
                              void* d_out, int out_size) {
    const float* emb  = (const float*)d_in[0];
    const int*   edge = (const int*)d_in[1];
    const int*   src  = edge;
    const int*   dst  = edge + N_EDGES;
    const int*   user = (const int*)d_in[2];
    const int*   pos  = (const int*)d_in[3];
    const int*   neg  = (const int*)d_in[4];
    float*       out  = (float*)d_out;

    const int T = 256;
    const int G_NODES = (N_NODES + T - 1) / T;
    const int G_EDGES = (N_EDGES + T - 1) / T;
    const int G_PROP  = (int)(((size_t)N_NODES * 32 + T - 1) / T);   // warp per node
    const int G_ACC   = (3 * BATCH * (DIM / 4) + T - 1) / T;
    const int G_MARK  = (3 * BATCH + T - 1) / T;

    // degree -> dinv
    k_init<<<G_NODES, T>>>();
    k_deg<<<G_EDGES, T>>>(dst);
    k_dinv<<<G_NODES, T>>>();

    // rowptr = exclusive scan(deg)
    k_scanA<<<N_SCAN_BLKS, SCAN_BLK>>>();
    k_scanB<<<1, 512>>>();
    k_scanC<<<G_NODES, T>>>();

    // CSR scatter (edge order within a dst is atomic-cursor nondeterministic; fp-sum
    // order differences are ~1e-7 relative, same class as atomic-RED baseline)
    k_scatter<<<G_EDGES, T>>>(src, dst);

    // needed-node flags: f3 = batch; f2 = batch ∪ src(in-edges of f3); f1 likewise from f2
    k_mark_batch<<<G_MARK, T>>>(user, pos, neg);
    k_expand<<<G_EDGES, T>>>(src, dst, g_f3, g_f2);
    k_expand<<<G_EDGES, T>>>(src, dst, g_f2, g_f1);

    // layer-0 term of the stacked mean
    k_init_acc<<<G_ACC, T>>>(emb, user, pos, neg);

    // layer 1: emb -> XA (only f1 rows)
    k_prop_csr<<<G_PROP, T>>>(emb, g_XA, g_f1);
    k_gather_add<<<G_ACC, T>>>(g_XA, user, pos, neg);

    // layer 2: XA -> XB (only f2 rows; their sources are all f1 rows)
    k_prop_csr<<<G_PROP, T>>>(g_XA, g_XB, g_f2);
    k_gather_add<<<G_ACC, T>>>(g_XB, user, pos, neg);

    // layer 3: XB -> XA (only f3 = batch rows)
    k_prop_csr<<<G_PROP, T>>>(g_XB, g_XA, g_f3);
    k_gather_add<<<G_ACC, T>>>(g_XA, user, pos, neg);

    // loss
    k_zero_out<<<1, 1>>>(out);
    k_loss<<<BATCH / 8, T>>>(emb, user, pos, neg, out);
}